// round 10
// baseline (speedup 1.0000x reference)
#include <cuda_runtime.h>
#include <cstdint>

#define B 8
#define T_IN 512
#define D 384
#define VPR (D / 4)          // 96 float4s per row
#define T_MEL 3584
#define MEL_MAX 2048
#define ROWS_PER_BLOCK 32
#define TILE_BYTES (ROWS_PER_BLOCK * D * 4)          // 49152 = 48KB
#define GATHER_GRID (B * MEL_MAX / ROWS_PER_BLOCK)   // 512

// frame -> token map (-1 = zero row)
__device__ int g_idx[B * MEL_MAX];

__device__ __forceinline__ uint32_t smem_u32(const void* p) {
    uint32_t a;
    asm("{ .reg .u64 t; cvta.to.shared.u64 t, %1; cvt.u32.u64 %0, t; }" : "=r"(a) : "l"(p));
    return a;
}

// ---------------- prep: shuffle scan + g_idx + pitch + dec_lens ----------------
__global__ void __launch_bounds__(512) prep_kernel(const int* __restrict__ dur,
                                                   const float* __restrict__ pitch,
                                                   float* __restrict__ dec_lens_out,
                                                   float* __restrict__ pitch_avg_out) {
    const int b = blockIdx.x;
    const int tid = threadIdx.x;

    __shared__ int cum[T_IN + 1];
    __shared__ int wsum[4];

    // init g_idx to -1 (independent of scan; overlaps with it)
    int* idx = g_idx + b * MEL_MAX;
    #pragma unroll
    for (int k = 0; k < 4; k++) idx[tid + 512 * k] = -1;

    if (tid < 128) {
        int4 dv = ((const int4*)(dur + b * T_IN))[tid];
        int s0 = dv.x, s1 = s0 + dv.y, s2 = s1 + dv.z, s3 = s2 + dv.w;
        int v = s3;
        const int wl = tid & 31;
        #pragma unroll
        for (int off = 1; off < 32; off <<= 1) {
            int n = __shfl_up_sync(0xffffffffu, v, off);
            if (wl >= off) v += n;
        }
        if (wl == 31) wsum[tid >> 5] = v;
        cum[4 * tid + 1] = v - s3 + s0;
        cum[4 * tid + 2] = v - s3 + s1;
        cum[4 * tid + 3] = v - s3 + s2;
        cum[4 * tid + 4] = v;
        if (tid == 0) cum[0] = 0;
    }
    __syncthreads();
    if (tid < 128) {
        const int wid = tid >> 5;
        int woff = 0;
        #pragma unroll
        for (int w = 0; w < 3; w++) if (w < wid) woff += wsum[w];
        if (woff) {
            cum[4 * tid + 1] += woff;
            cum[4 * tid + 2] += woff;
            cum[4 * tid + 3] += woff;
            cum[4 * tid + 4] += woff;
        }
    }
    __syncthreads();

    const int start = cum[tid];
    const int end = cum[tid + 1];

    if (tid == 0) {
        int total = cum[T_IN];
        dec_lens_out[b] = (float)(total < MEL_MAX ? total : MEL_MAX);
    }

    // g_idx range fill: ≤7 predicated independent stores
    const int e = end < MEL_MAX ? end : MEL_MAX;
    #pragma unroll
    for (int k = 0; k < 7; k++) {
        const int m = start + k;
        if (m < e) idx[m] = tid;
    }

    // pitch average: ≤7 predicated independent loads (N_FORMANTS = 1)
    {
        const float* p = pitch + (size_t)b * T_MEL;
        float s = 0.0f, cnt = 0.0f;
        #pragma unroll
        for (int k = 0; k < 7; k++) {
            const int m = start + k;
            if (m < end) {
                float x = __ldg(&p[m]);
                s += x;
                if (x != 0.0f) cnt += 1.0f;
            }
        }
        pitch_avg_out[b * T_IN + tid] = (cnt != 0.0f) ? (s / cnt) : 0.0f;
    }
}

// ---------------- gather: stage 32 rows in smem, one bulk-async store per block ----
// block = 384 threads = 4 row-groups x 96 lanes; 8 rows per row-group (stride 4).
__global__ void __launch_bounds__(384) gather_kernel(const float* __restrict__ enc,
                                                     float* __restrict__ out) {
    __shared__ float4 buf[ROWS_PER_BLOCK * VPR];     // 48KB staging tile

    const int lane = threadIdx.x % VPR;
    const int rsub = threadIdx.x / VPR;              // 0..3
    const int row0 = blockIdx.x * ROWS_PER_BLOCK + rsub;
    const int b = blockIdx.x >> 6;                   // 64 blocks per batch

    // phase 1: 8 independent idx loads
    int t[8];
    #pragma unroll
    for (int k = 0; k < 8; k++) t[k] = __ldg(&g_idx[row0 + 4 * k]);

    // phase 2: 8 independent gathers
    const float4* encb = (const float4*)enc + (size_t)b * T_IN * VPR + lane;
    float4 v[8];
    #pragma unroll
    for (int k = 0; k < 8; k++) {
        v[k] = (t[k] >= 0) ? __ldg(encb + (size_t)t[k] * VPR)
                           : make_float4(0.f, 0.f, 0.f, 0.f);
    }

    // phase 3: stage to smem (cheap STS.128, no global scoreboard)
    #pragma unroll
    for (int k = 0; k < 8; k++)
        buf[(rsub + 4 * k) * VPR + lane] = v[k];

    __syncthreads();
    asm volatile("fence.proxy.async.shared::cta;" ::: "memory");

    // phase 4: single 48KB bulk-async store of the contiguous tile
    if (threadIdx.x == 0) {
        const uint32_t s = smem_u32(buf);
        float* dst = out + (size_t)blockIdx.x * ROWS_PER_BLOCK * D;
        asm volatile("cp.async.bulk.global.shared::cta.bulk_group [%0], [%1], %2;"
                     :: "l"(dst), "r"(s), "n"(TILE_BYTES) : "memory");
        asm volatile("cp.async.bulk.commit_group;" ::: "memory");
        asm volatile("cp.async.bulk.wait_group 0;" ::: "memory");
    }
}

extern "C" void kernel_launch(void* const* d_in, const int* in_sizes, int n_in,
                              void* d_out, int out_size) {
    const float* enc_out = (const float*)d_in[0];   // [B, T_IN, D]
    const int* durations = (const int*)d_in[1];     // [B, T_IN]
    const float* pitch = (const float*)d_in[2];     // [B, 1, T_MEL]

    float* out = (float*)d_out;
    float* enc_rep = out;                               // B*MEL_MAX*D
    float* dec_lens = out + (size_t)B * MEL_MAX * D;    // B
    float* pitch_avg = dec_lens + B;                    // B*T_IN

    prep_kernel<<<B, 512>>>(durations, pitch, dec_lens, pitch_avg);
    gather_kernel<<<GATHER_GRID, 384>>>(enc_out, enc_rep);
}

// round 11
// speedup vs baseline: 1.1243x; 1.1243x over previous
#include <cuda_runtime.h>

#define B 8
#define T_IN 512
#define D 384
#define VPR (D / 4)          // 96 float4s per row
#define T_MEL 3584
#define MEL_MAX 2048
#define GTHREADS 192         // 2 row-groups x 96 lanes
#define ROWS_PER_BLOCK 8     // 4 rows per thread (stride 2)
#define GATHER_GRID (B * MEL_MAX / ROWS_PER_BLOCK)   // 2048

// frame -> token map (-1 = zero row)
__device__ int g_idx[B * MEL_MAX];

// ---------------- prep: shuffle scan + g_idx + pitch + dec_lens ----------------
__global__ void __launch_bounds__(512) prep_kernel(const int* __restrict__ dur,
                                                   const float* __restrict__ pitch,
                                                   float* __restrict__ dec_lens_out,
                                                   float* __restrict__ pitch_avg_out) {
    const int b = blockIdx.x;
    const int tid = threadIdx.x;

    __shared__ int cum[T_IN + 1];
    __shared__ int wsum[4];

    // init g_idx to -1 (independent of scan; overlaps with it)
    int* idx = g_idx + b * MEL_MAX;
    #pragma unroll
    for (int k = 0; k < 4; k++) idx[tid + 512 * k] = -1;

    if (tid < 128) {
        int4 dv = ((const int4*)(dur + b * T_IN))[tid];
        int s0 = dv.x, s1 = s0 + dv.y, s2 = s1 + dv.z, s3 = s2 + dv.w;
        int v = s3;
        const int wl = tid & 31;
        #pragma unroll
        for (int off = 1; off < 32; off <<= 1) {
            int n = __shfl_up_sync(0xffffffffu, v, off);
            if (wl >= off) v += n;
        }
        if (wl == 31) wsum[tid >> 5] = v;
        cum[4 * tid + 1] = v - s3 + s0;
        cum[4 * tid + 2] = v - s3 + s1;
        cum[4 * tid + 3] = v - s3 + s2;
        cum[4 * tid + 4] = v;
        if (tid == 0) cum[0] = 0;
    }
    __syncthreads();
    if (tid < 128) {
        const int wid = tid >> 5;
        int woff = 0;
        #pragma unroll
        for (int w = 0; w < 3; w++) if (w < wid) woff += wsum[w];
        if (woff) {
            cum[4 * tid + 1] += woff;
            cum[4 * tid + 2] += woff;
            cum[4 * tid + 3] += woff;
            cum[4 * tid + 4] += woff;
        }
    }
    __syncthreads();

    const int start = cum[tid];
    const int end = cum[tid + 1];

    if (tid == 0) {
        int total = cum[T_IN];
        dec_lens_out[b] = (float)(total < MEL_MAX ? total : MEL_MAX);
    }

    // g_idx range fill: ≤7 predicated independent stores
    const int e = end < MEL_MAX ? end : MEL_MAX;
    #pragma unroll
    for (int k = 0; k < 7; k++) {
        const int m = start + k;
        if (m < e) idx[m] = tid;
    }

    // pitch average: ≤7 predicated independent loads (N_FORMANTS = 1)
    {
        const float* p = pitch + (size_t)b * T_MEL;
        float s = 0.0f, cnt = 0.0f;
        #pragma unroll
        for (int k = 0; k < 7; k++) {
            const int m = start + k;
            if (m < end) {
                float x = __ldg(&p[m]);
                s += x;
                if (x != 0.0f) cnt += 1.0f;
            }
        }
        pitch_avg_out[b * T_IN + tid] = (cnt != 0.0f) ? (s / cnt) : 0.0f;
    }
}

// ---------------- gather: high-occupancy + 4 chains/thread ----------------
// block = 192 threads = 2 row-groups x 96 lanes; block covers 8 rows (stride 2).
__global__ void __launch_bounds__(GTHREADS) gather_kernel(const float* __restrict__ enc,
                                                          float* __restrict__ out) {
    const int lane = threadIdx.x % VPR;
    const int rsub = threadIdx.x / VPR;              // 0..1
    const int row0 = blockIdx.x * ROWS_PER_BLOCK + rsub;
    const int b = blockIdx.x >> 8;                   // 256 blocks per batch

    // phase 1: 4 independent idx loads
    int t[4];
    #pragma unroll
    for (int k = 0; k < 4; k++) t[k] = __ldg(&g_idx[row0 + 2 * k]);

    // phase 2: 4 independent gathers
    const float4* encb = (const float4*)enc + (size_t)b * T_IN * VPR + lane;
    float4 v[4];
    #pragma unroll
    for (int k = 0; k < 4; k++) {
        v[k] = (t[k] >= 0) ? __ldg(encb + (size_t)t[k] * VPR)
                           : make_float4(0.f, 0.f, 0.f, 0.f);
    }

    // phase 3: 4 coalesced independent stores
    float4* outp = (float4*)out + (size_t)row0 * VPR + lane;
    #pragma unroll
    for (int k = 0; k < 4; k++) outp[(size_t)(2 * k) * VPR] = v[k];
}

extern "C" void kernel_launch(void* const* d_in, const int* in_sizes, int n_in,
                              void* d_out, int out_size) {
    const float* enc_out = (const float*)d_in[0];   // [B, T_IN, D]
    const int* durations = (const int*)d_in[1];     // [B, T_IN]
    const float* pitch = (const float*)d_in[2];     // [B, 1, T_MEL]

    float* out = (float*)d_out;
    float* enc_rep = out;                               // B*MEL_MAX*D
    float* dec_lens = out + (size_t)B * MEL_MAX * D;    // B
    float* pitch_avg = dec_lens + B;                    // B*T_IN

    prep_kernel<<<B, 512>>>(durations, pitch, dec_lens, pitch_avg);
    gather_kernel<<<GATHER_GRID, GTHREADS>>>(enc_out, enc_rep);
}